// round 14
// baseline (speedup 1.0000x reference)
#include <cuda_runtime.h>
#include <math.h>

#define BB 128
#define TT 1024
#define DD 512
#define HH 512

// ---------------- scratch ----------------
__device__ float g_xp[(size_t)TT * BB * HH];   // [t][b][h]
__device__ float g_h[2][BB * HH];              // ping-pong hidden state
__device__ unsigned g_flag[8 * 16 * 32];       // flag[mg][ng] at 128B stride
__device__ unsigned g_ctr[8 * 32];
__device__ unsigned g_gen[8 * 32];

__device__ __forceinline__ unsigned long long ffma2(unsigned long long a,
                                                    unsigned long long b,
                                                    unsigned long long c) {
    unsigned long long d;
    asm("fma.rn.f32x2 %0, %1, %2, %3;" : "=l"(d) : "l"(a), "l"(b), "l"(c));
    return d;
}
__device__ __forceinline__ unsigned long long pack2(float x, float y) {
    unsigned long long d;
    asm("mov.b64 %0, {%1, %2};" : "=l"(d) : "f"(x), "f"(y));
    return d;
}
__device__ __forceinline__ void unpack2(unsigned long long v, float& x, float& y) {
    asm("mov.b64 {%0, %1}, %2;" : "=f"(x), "=f"(y) : "l"(v));
}

__device__ __forceinline__ unsigned atom_add_acqrel(unsigned* p, unsigned v) {
    unsigned old;
    asm volatile("atom.acq_rel.gpu.global.add.u32 %0, [%1], %2;"
                 : "=r"(old) : "l"(p), "r"(v) : "memory");
    return old;
}
__device__ __forceinline__ unsigned ld_acquire(unsigned* p) {
    unsigned v;
    asm volatile("ld.acquire.gpu.global.u32 %0, [%1];"
                 : "=r"(v) : "l"(p) : "memory");
    return v;
}
__device__ __forceinline__ void st_relaxed(unsigned* p, unsigned v) {
    asm volatile("st.relaxed.gpu.global.u32 [%0], %1;"
                 :: "l"(p), "r"(v) : "memory");
}
__device__ __forceinline__ void fence_rel_gpu() {
    asm volatile("fence.release.gpu;" ::: "memory");
}

__device__ __forceinline__ void group_barrier(int tid, unsigned* ctr, unsigned* gen) {
    __syncthreads();
    if (tid == 0) {
        unsigned g = ld_acquire(gen);
        unsigned tk = atom_add_acqrel(ctr, 1u);
        if (tk == 15u) {
            st_relaxed(ctr, 0u);
            atom_add_acqrel(gen, 1u);
        } else {
            while (ld_acquire(gen) == g) { }
        }
    }
    __syncthreads();
}

// =====================================================================
// Phase 1: xp = x @ W_ih + b   (unchanged)
// =====================================================================
__global__ void __launch_bounds__(256) xp_gemm_kernel(
        const float* __restrict__ x, const float* __restrict__ Wih,
        const float* __restrict__ bias) {
    __shared__ float As[16][128];
    __shared__ float Bs[16][128];

    const int tid = threadIdx.x;
    const int tx = tid & 15;
    const int ty = tid >> 4;
    const int m0 = blockIdx.y * 128;
    const int n0 = blockIdx.x * 128;

    unsigned long long acc[8][4];
#pragma unroll
    for (int i = 0; i < 8; i++)
#pragma unroll
        for (int j = 0; j < 4; j++) acc[i][j] = 0ull;

    for (int k0 = 0; k0 < DD; k0 += 16) {
#pragma unroll
        for (int q = 0; q < 2; q++) {
            int i = tid + q * 256;
            int row = i >> 2;
            int kc = (i & 3) * 4;
            float4 av = *(const float4*)&x[(size_t)(m0 + row) * DD + k0 + kc];
            As[kc + 0][row] = av.x;
            As[kc + 1][row] = av.y;
            As[kc + 2][row] = av.z;
            As[kc + 3][row] = av.w;
        }
#pragma unroll
        for (int q = 0; q < 2; q++) {
            int i = tid + q * 256;
            int kr = i >> 5;
            int nc = (i & 31) * 4;
            float4 bv = *(const float4*)&Wih[(size_t)(k0 + kr) * HH + n0 + nc];
            *(float4*)&Bs[kr][nc] = bv;
        }
        __syncthreads();

#pragma unroll
        for (int kk = 0; kk < 16; kk++) {
            float4 a0 = *(const float4*)&As[kk][ty * 8];
            float4 a1 = *(const float4*)&As[kk][ty * 8 + 4];
            const unsigned long long* bp =
                (const unsigned long long*)&Bs[kk][tx * 8];
            unsigned long long b0 = bp[0], b1 = bp[1], b2 = bp[2], b3 = bp[3];
            float a[8] = {a0.x, a0.y, a0.z, a0.w, a1.x, a1.y, a1.z, a1.w};
#pragma unroll
            for (int i = 0; i < 8; i++) {
                unsigned long long ap = pack2(a[i], a[i]);
                acc[i][0] = ffma2(ap, b0, acc[i][0]);
                acc[i][1] = ffma2(ap, b1, acc[i][1]);
                acc[i][2] = ffma2(ap, b2, acc[i][2]);
                acc[i][3] = ffma2(ap, b3, acc[i][3]);
            }
        }
        __syncthreads();
    }

    float4 bv0 = *(const float4*)&bias[n0 + tx * 8];
    float4 bv1 = *(const float4*)&bias[n0 + tx * 8 + 4];
    float bb8[8] = {bv0.x, bv0.y, bv0.z, bv0.w, bv1.x, bv1.y, bv1.z, bv1.w};
#pragma unroll
    for (int i = 0; i < 8; i++) {
        int mrow = m0 + ty * 8 + i;
        int b_ = mrow >> 10;
        int t_ = mrow & 1023;
        float f[8];
        unpack2(acc[i][0], f[0], f[1]);
        unpack2(acc[i][1], f[2], f[3]);
        unpack2(acc[i][2], f[4], f[5]);
        unpack2(acc[i][3], f[6], f[7]);
#pragma unroll
        for (int j = 0; j < 8; j++) f[j] += bb8[j];
        float* dst = &g_xp[((size_t)t_ * BB + b_) * HH + n0 + tx * 8];
        *(float4*)&dst[0] = make_float4(f[0], f[1], f[2], f[3]);
        *(float4*)&dst[4] = make_float4(f[4], f[5], f[6], f[7]);
    }
}

// =====================================================================
// Phase 2 v8: per-chunk dataflow flags — no in-loop group barrier.
// Warp w consumes exactly the slice produced by CTA (mg,w).
// Row chunk in smem: 8 f4 = 8 ull2; ull2 m = k-pairs (wr[2m], wr[2m+1]).
// =====================================================================
__global__ void __launch_bounds__(512) rnn_steps_kernel(
        const float* __restrict__ Whh, float* __restrict__ out) {
    extern __shared__ float smemf[];
    float4* hs4 = (float4*)smemf;            // [16 warps][128 f4] = 32 KB
    float*  pb  = smemf + 2048 * 4;          // [16 warps][16 rows][32] = 32 KB

    const int tid = threadIdx.x;
    const int warp = tid >> 5, lane = tid & 31;

    const int mg = blockIdx.x >> 4;
    const int ng = blockIdx.x & 15;
    const int row0 = mg * 16;
    const int col0 = ng * 32;

    const int col = col0 + lane;
    const int k0w = warp * 32;

    unsigned long long wr[16];
#pragma unroll
    for (int kk = 0; kk < 16; kk++) {
        const float* p = Whh + (size_t)(k0w + 2 * kk) * HH + col;
        wr[kk] = pack2(p[0], p[HH]);
    }

    const int orow = row0 + warp;
    const int ocol = col0 + lane;

    unsigned* myflag = &g_flag[(mg * 16 + ng) * 32];
    unsigned* wflag  = &g_flag[(mg * 16 + warp) * 32];

    const int lr = lane >> 3;                // 0..3
    const int lj = lane & 7;                 // 0..7

    // ---------------- t = 0 (h = 0) ----------------
    {
        float xv = __ldcg(&g_xp[(size_t)orow * HH + ocol]);
        float hv = tanhf(xv);
        g_h[1][(size_t)orow * HH + ocol] = hv;
        __syncthreads();
        if (tid == 0) { fence_rel_gpu(); st_relaxed(myflag, 1u); }
    }

    float xv = __ldcg(&g_xp[((size_t)1 * BB + orow) * HH + ocol]);

    for (int t = 1; t < TT; t++) {
        while (ld_acquire(wflag) < (unsigned)t) { }

        const float4* hsrc = (const float4*)g_h[t & 1];
#pragma unroll
        for (int i = 0; i < 4; i++) {
            int r = lr + i * 4;
            hs4[warp * 128 + r * 8 + lj] =
                __ldcg(hsrc + (size_t)(row0 + r) * 128 + warp * 8 + lj);
        }
        float xv_next = 0.0f;
        if (t + 1 < TT)
            xv_next = __ldcg(&g_xp[((size_t)(t + 1) * BB + orow) * HH + ocol]);
        __syncwarp();

        unsigned long long acc[16];
#pragma unroll
        for (int r = 0; r < 16; r++) acc[r] = 0ull;

        const ulonglong2* hbase = (const ulonglong2*)(hs4 + warp * 128);
#pragma unroll
        for (int r = 0; r < 16; r++) {
            const ulonglong2* hp = hbase + r * 8;     // 8 ull2 per row (16 f4? no: 8 f4 = 8 ull2? f4=16B=ull2 ✓)
#pragma unroll
            for (int m = 0; m < 8; m += 2) {
                ulonglong2 h0 = hp[m >> 1];           // WRONG? see mapping below
                acc[r] = ffma2(h0.x, wr[m], acc[r]);
                acc[r] = ffma2(h0.y, wr[m + 1], acc[r]);
            }
        }

#pragma unroll
        for (int r = 0; r < 16; r++) {
            const ulonglong2* hp = hbase + r * 8 + 4;
#pragma unroll
            for (int m = 8; m < 16; m += 2) {
                ulonglong2 h0 = hp[(m - 8) >> 1];
                acc[r] = ffma2(h0.x, wr[m], acc[r]);
                acc[r] = ffma2(h0.y, wr[m + 1], acc[r]);
            }
        }

#pragma unroll
        for (int r = 0; r < 16; r++) {
            float a, b;
            unpack2(acc[r], a, b);
            pb[(warp * 16 + r) * 32 + lane] = a + b;
        }
        __syncthreads();

        float s = 0.0f;
#pragma unroll
        for (int w2 = 0; w2 < 16; w2++) s += pb[(w2 * 16 + warp) * 32 + lane];

        float hv = tanhf(xv + s);
        g_h[(t + 1) & 1][(size_t)orow * HH + ocol] = hv;
        if (t == TT - 1) out[(size_t)orow * HH + ocol] = hv;

        __syncthreads();
        if (t + 1 < TT && tid == 0) {
            fence_rel_gpu();
            st_relaxed(myflag, (unsigned)(t + 1));
        }
        xv = xv_next;
    }

    if (tid == 0) st_relaxed(myflag, 0u);
    group_barrier(tid, &g_ctr[mg * 32], &g_gen[mg * 32]);
}

extern "C" void kernel_launch(void* const* d_in, const int* in_sizes, int n_in,
                              void* d_out, int out_size) {
    const float* x    = (const float*)d_in[0];
    const float* Wih  = (const float*)d_in[1];
    const float* Whh  = (const float*)d_in[2];
    const float* bias = (const float*)d_in[3];
    float* out = (float*)d_out;

    const int smem2 = 2048 * 16 + 8192 * 4;   // 64 KB
    cudaFuncSetAttribute(rnn_steps_kernel,
                         cudaFuncAttributeMaxDynamicSharedMemorySize, smem2);

    dim3 g1(HH / 128, (BB * TT) / 128);   // (4, 1024)
    xp_gemm_kernel<<<g1, 256>>>(x, Wih, bias);
    rnn_steps_kernel<<<128, 512, smem2>>>(Whh, out);
}

// round 15
// speedup vs baseline: 1.8272x; 1.8272x over previous
#include <cuda_runtime.h>
#include <math.h>

#define BB 128
#define TT 1024
#define DD 512
#define HH 512

// ---------------- scratch ----------------
__device__ float g_xp[(size_t)TT * BB * HH];   // [t][b][h]
__device__ float g_h[2][BB * HH];              // ping-pong hidden state
__device__ unsigned g_flag[16 * 16 * 32];      // flag[mg][ng] at 128B stride
__device__ unsigned g_ctr[16 * 32];
__device__ unsigned g_gen[16 * 32];

__device__ __forceinline__ unsigned long long ffma2(unsigned long long a,
                                                    unsigned long long b,
                                                    unsigned long long c) {
    unsigned long long d;
    asm("fma.rn.f32x2 %0, %1, %2, %3;" : "=l"(d) : "l"(a), "l"(b), "l"(c));
    return d;
}
__device__ __forceinline__ unsigned long long pack2(float x, float y) {
    unsigned long long d;
    asm("mov.b64 %0, {%1, %2};" : "=l"(d) : "f"(x), "f"(y));
    return d;
}
__device__ __forceinline__ void unpack2(unsigned long long v, float& x, float& y) {
    asm("mov.b64 {%0, %1}, %2;" : "=f"(x), "=f"(y) : "l"(v));
}

__device__ __forceinline__ unsigned atom_add_acqrel(unsigned* p, unsigned v) {
    unsigned old;
    asm volatile("atom.acq_rel.gpu.global.add.u32 %0, [%1], %2;"
                 : "=r"(old) : "l"(p), "r"(v) : "memory");
    return old;
}
__device__ __forceinline__ unsigned ld_acquire(unsigned* p) {
    unsigned v;
    asm volatile("ld.acquire.gpu.global.u32 %0, [%1];"
                 : "=r"(v) : "l"(p) : "memory");
    return v;
}
__device__ __forceinline__ void st_relaxed(unsigned* p, unsigned v) {
    asm volatile("st.relaxed.gpu.global.u32 [%0], %1;"
                 :: "l"(p), "r"(v) : "memory");
}
__device__ __forceinline__ void fence_rel_gpu() {
    asm volatile("fence.release.gpu;" ::: "memory");
}

__device__ __forceinline__ void group_barrier(int tid, unsigned* ctr, unsigned* gen) {
    __syncthreads();
    if (tid == 0) {
        unsigned g = ld_acquire(gen);
        unsigned tk = atom_add_acqrel(ctr, 1u);
        if (tk == 15u) {
            st_relaxed(ctr, 0u);
            atom_add_acqrel(gen, 1u);
        } else {
            while (ld_acquire(gen) == g) { }
        }
    }
    __syncthreads();
}

// =====================================================================
// Phase 1: xp = x @ W_ih + b   (unchanged)
// =====================================================================
__global__ void __launch_bounds__(256) xp_gemm_kernel(
        const float* __restrict__ x, const float* __restrict__ Wih,
        const float* __restrict__ bias) {
    __shared__ float As[16][128];
    __shared__ float Bs[16][128];

    const int tid = threadIdx.x;
    const int tx = tid & 15;
    const int ty = tid >> 4;
    const int m0 = blockIdx.y * 128;
    const int n0 = blockIdx.x * 128;

    unsigned long long acc[8][4];
#pragma unroll
    for (int i = 0; i < 8; i++)
#pragma unroll
        for (int j = 0; j < 4; j++) acc[i][j] = 0ull;

    for (int k0 = 0; k0 < DD; k0 += 16) {
#pragma unroll
        for (int q = 0; q < 2; q++) {
            int i = tid + q * 256;
            int row = i >> 2;
            int kc = (i & 3) * 4;
            float4 av = *(const float4*)&x[(size_t)(m0 + row) * DD + k0 + kc];
            As[kc + 0][row] = av.x;
            As[kc + 1][row] = av.y;
            As[kc + 2][row] = av.z;
            As[kc + 3][row] = av.w;
        }
#pragma unroll
        for (int q = 0; q < 2; q++) {
            int i = tid + q * 256;
            int kr = i >> 5;
            int nc = (i & 31) * 4;
            float4 bv = *(const float4*)&Wih[(size_t)(k0 + kr) * HH + n0 + nc];
            *(float4*)&Bs[kr][nc] = bv;
        }
        __syncthreads();

#pragma unroll
        for (int kk = 0; kk < 16; kk++) {
            float4 a0 = *(const float4*)&As[kk][ty * 8];
            float4 a1 = *(const float4*)&As[kk][ty * 8 + 4];
            const unsigned long long* bp =
                (const unsigned long long*)&Bs[kk][tx * 8];
            unsigned long long b0 = bp[0], b1 = bp[1], b2 = bp[2], b3 = bp[3];
            float a[8] = {a0.x, a0.y, a0.z, a0.w, a1.x, a1.y, a1.z, a1.w};
#pragma unroll
            for (int i = 0; i < 8; i++) {
                unsigned long long ap = pack2(a[i], a[i]);
                acc[i][0] = ffma2(ap, b0, acc[i][0]);
                acc[i][1] = ffma2(ap, b1, acc[i][1]);
                acc[i][2] = ffma2(ap, b2, acc[i][2]);
                acc[i][3] = ffma2(ap, b3, acc[i][3]);
            }
        }
        __syncthreads();
    }

    float4 bv0 = *(const float4*)&bias[n0 + tx * 8];
    float4 bv1 = *(const float4*)&bias[n0 + tx * 8 + 4];
    float bb8[8] = {bv0.x, bv0.y, bv0.z, bv0.w, bv1.x, bv1.y, bv1.z, bv1.w};
#pragma unroll
    for (int i = 0; i < 8; i++) {
        int mrow = m0 + ty * 8 + i;
        int b_ = mrow >> 10;
        int t_ = mrow & 1023;
        float f[8];
        unpack2(acc[i][0], f[0], f[1]);
        unpack2(acc[i][1], f[2], f[3]);
        unpack2(acc[i][2], f[4], f[5]);
        unpack2(acc[i][3], f[6], f[7]);
#pragma unroll
        for (int j = 0; j < 8; j++) f[j] += bb8[j];
        float* dst = &g_xp[((size_t)t_ * BB + b_) * HH + n0 + tx * 8];
        *(float4*)&dst[0] = make_float4(f[0], f[1], f[2], f[3]);
        *(float4*)&dst[4] = make_float4(f[4], f[5], f[6], f[7]);
    }
}

// =====================================================================
// Phase 2 v9: 256 CTAs x 256 thr (8 rows x 32 cols), 2 CTAs/SM.
// Warp w: k-slice w*64..+63. Lane = (kh = lane>>4, c2 = lane&15):
// thread covers 2 cols (2*c2, 2*c2+1) and 32 k. Each LDS.128 of h
// feeds 4 FFMA2. Per-warp producer flags (producers 2w, 2w+1).
// 16 m-groups of 8 rows; flags reset AFTER the end barrier.
// =====================================================================
__global__ void __launch_bounds__(256, 2) rnn_steps_kernel(
        const float* __restrict__ Whh, float* __restrict__ out) {
    extern __shared__ float smemf[];
    float4* hs4 = (float4*)smemf;            // [8 rows][128 f4] = 16 KB
    float*  pb  = smemf + 1024 * 4;          // [16 pid][8 rows][32 cols] = 16 KB

    const int tid = threadIdx.x;
    const int warp = tid >> 5, lane = tid & 31;
    const int c2 = lane & 15;                // col-pair index
    const int kh = lane >> 4;                // k-half within warp slice

    const int mg = blockIdx.x >> 4;          // 0..15 (8 rows each)
    const int ng = blockIdx.x & 15;          // 0..15 (32 cols each)
    const int row0 = mg * 8;
    const int col0 = ng * 32;

    const int col = col0 + 2 * c2;           // this thread's first col
    const int k0 = warp * 64 + kh * 32;      // this thread's k base

    // ---- one-time W load: w2[kk][c] = (W[k0+2kk][col+c], W[k0+2kk+1][col+c])
    unsigned long long w2[16][2];
#pragma unroll
    for (int kk = 0; kk < 16; kk++) {
        const float* p0 = Whh + (size_t)(k0 + 2 * kk) * HH + col;
        const float* p1 = p0 + HH;
        w2[kk][0] = pack2(p0[0], p1[0]);
        w2[kk][1] = pack2(p0[1], p1[1]);
    }

    const int orow = row0 + warp;            // output: row = warp, col = lane
    const int ocol = col0 + lane;

    unsigned* myflag = &g_flag[(mg * 16 + ng) * 32];
    unsigned* f0 = &g_flag[(mg * 16 + 2 * warp) * 32];
    unsigned* f1 = &g_flag[(mg * 16 + 2 * warp + 1) * 32];

    const int lr = lane >> 4;                // 0..1 (row offset for chunk load)
    const int lj = lane & 15;                // 0..15 (f4 within warp chunk)

    // ---------------- t = 0 (h = 0) ----------------
    {
        float xv = __ldcg(&g_xp[(size_t)orow * HH + ocol]);
        float hv = tanhf(xv);
        g_h[1][(size_t)orow * HH + ocol] = hv;
        __syncthreads();
        if (tid == 0) { fence_rel_gpu(); st_relaxed(myflag, 1u); }
    }

    float xv = __ldcg(&g_xp[((size_t)1 * BB + orow) * HH + ocol]);

    // ---------------- t = 1 .. TT-1 ----------------
    for (int t = 1; t < TT; t++) {
        // wait for this warp's two producers
        while (ld_acquire(f0) < (unsigned)t) { }
        while (ld_acquire(f1) < (unsigned)t) { }

        // load warp's k-chunk: 8 rows x 16 f4 (f4 base = warp*16)
        const float4* hsrc = (const float4*)g_h[t & 1];
#pragma unroll
        for (int i = 0; i < 4; i++) {
            int r = lr + 2 * i;              // rows lr, lr+2, lr+4, lr+6
            hs4[r * 128 + warp * 16 + lj] =
                __ldcg(hsrc + (size_t)(row0 + r) * 128 + warp * 16 + lj);
        }
        float xv_next = 0.0f;
        if (t + 1 < TT)
            xv_next = __ldcg(&g_xp[((size_t)(t + 1) * BB + orow) * HH + ocol]);
        __syncwarp();

        // ---- compute: acc[r][c] over this thread's 32 k
        unsigned long long acc[8][2];
#pragma unroll
        for (int r = 0; r < 8; r++) { acc[r][0] = 0ull; acc[r][1] = 0ull; }

        const ulonglong2* hsU = (const ulonglong2*)hs4;
#pragma unroll
        for (int r = 0; r < 8; r++) {
            const ulonglong2* hp = hsU + r * 128 + warp * 16 + kh * 8;
#pragma unroll
            for (int j = 0; j < 8; j++) {
                ulonglong2 hv2 = hp[j];      // k = k0+4j..k0+4j+3
                acc[r][0] = ffma2(hv2.x, w2[2 * j][0], acc[r][0]);
                acc[r][1] = ffma2(hv2.x, w2[2 * j][1], acc[r][1]);
                acc[r][0] = ffma2(hv2.y, w2[2 * j + 1][0], acc[r][0]);
                acc[r][1] = ffma2(hv2.y, w2[2 * j + 1][1], acc[r][1]);
            }
        }

        // ---- fold k-pairs, store partials pb[pid][r][cols 2c2, 2c2+1]
        const int pid = warp * 2 + kh;       // 0..15
        float2* pb2 = (float2*)pb;
#pragma unroll
        for (int r = 0; r < 8; r++) {
            float a, b, c, d;
            unpack2(acc[r][0], a, b);
            unpack2(acc[r][1], c, d);
            pb2[(pid * 8 + r) * 16 + c2] = make_float2(a + b, c + d);
        }
        __syncthreads();

        // ---- owner (row = warp, col = lane) reduces 16 partials
        float s = 0.0f;
#pragma unroll
        for (int p = 0; p < 16; p++) s += pb[(p * 8 + warp) * 32 + lane];

        float hv = tanhf(xv + s);
        g_h[(t + 1) & 1][(size_t)orow * HH + ocol] = hv;
        if (t == TT - 1) out[(size_t)orow * HH + ocol] = hv;

        __syncthreads();
        if (t + 1 < TT && tid == 0) {
            fence_rel_gpu();
            st_relaxed(myflag, (unsigned)(t + 1));
        }
        xv = xv_next;
    }

    // barrier FIRST (all polls in the group done), THEN reset for replay
    group_barrier(tid, &g_ctr[mg * 32], &g_gen[mg * 32]);
    if (tid == 0) st_relaxed(myflag, 0u);
}

// =====================================================================
extern "C" void kernel_launch(void* const* d_in, const int* in_sizes, int n_in,
                              void* d_out, int out_size) {
    const float* x    = (const float*)d_in[0];
    const float* Wih  = (const float*)d_in[1];
    const float* Whh  = (const float*)d_in[2];
    const float* bias = (const float*)d_in[3];
    float* out = (float*)d_out;

    const int smem2 = 1024 * 16 + 4096 * 4;   // 16KB h + 16KB partials = 32 KB
    cudaFuncSetAttribute(rnn_steps_kernel,
                         cudaFuncAttributeMaxDynamicSharedMemorySize, smem2);

    dim3 g1(HH / 128, (BB * TT) / 128);   // (4, 1024)
    xp_gemm_kernel<<<g1, 256>>>(x, Wih, bias);
    rnn_steps_kernel<<<256, 256, smem2>>>(Whh, out);
}